// round 17
// baseline (speedup 1.0000x reference)
#include <cuda_runtime.h>
#include <cuda_bf16.h>

#define KK 26
#define DD 128
#define MM 256
#define BB 512
#define WB  256          // word blocks (2 words each)
#define NRED 126         // reducer blocks (126*32 >= 4004 outputs)
#define NT  512          // 16 warps, 1 block/SM -> 125 regs/thread
#define KP 28            // padded row stride (8B-aligned rows)
#define WPAD 130         // padded W row stride
#define OUTSZ (KK*DD + KK*KK)   // 4004

typedef unsigned long long u64;

__device__ float g_scratch[BB * OUTSZ];   // per-word gradients
__device__ int g_ctr  = 0;                // word-completion doorbell
__device__ int g_done = 0;                // reducer-completion counter

// ---- packed f32x2 helpers (FFMA2 path, sm_100a) ----
__device__ __forceinline__ u64 ffma2(u64 a, u64 b, u64 c) {
    u64 d;
    asm("fma.rn.f32x2 %0, %1, %2, %3;" : "=l"(d) : "l"(a), "l"(b), "l"(c));
    return d;
}
__device__ __forceinline__ u64 pk2(float lo, float hi) {
    u64 r; asm("mov.b64 %0, {%1, %2};" : "=l"(r) : "f"(lo), "f"(hi)); return r;
}
__device__ __forceinline__ float2 upk2(u64 v) {
    float2 f; asm("mov.b64 {%0, %1}, %2;" : "=f"(f.x), "=f"(f.y) : "l"(v)); return f;
}
__device__ __forceinline__ int ld_vol(const int* p) {
    int v; asm volatile("ld.volatile.global.s32 %0, [%1];" : "=r"(v) : "l"(p)); return v;
}

// ---- dynamic shared memory layout (floats): two word-sets ----
#define SM_PSA  0
#define SM_UA   (SM_PSA + MM*KP)
#define SM_VA   (SM_UA  + MM*KP)
#define SM_PSB  (SM_VA  + MM*KP)
#define SM_UB   (SM_PSB + MM*KP)
#define SM_VB   (SM_UB  + MM*KP)        // Wsh aliases here (dead before DP_B writes V_B)
#define SM_E    (SM_VB  + MM*KP)        // 43008
#define SM_LABA (SM_E   + KK*KK)
#define SM_LABB (SM_LABA + MM)
#define SM_DEA  (SM_LABB + MM)
#define SM_DEB  (SM_DEA  + MM)
#define SM_CNTA (SM_DEB  + MM)
#define SM_CNTB (SM_CNTA + KK*KK)
#define SM_TOT  (SM_CNTB + KK*KK)       // 46060 floats = 184240 bytes

// ================= phase bodies (R16-identical, re-strided) =================

__device__ __forceinline__ void phase_S(const float* __restrict__ x, float* Ps,
                                        const float* Wsh, int g0, int ng, int lane)
{
    const int ll = (lane < KK) ? lane : 0;
    const u64* wr = (const u64*)(Wsh + ll * WPAD);
    for (int g = g0; g < 32; g += ng) {
        const int ib = g * 8;
        const double2* xb = (const double2*)(x + (size_t)ib * DD);
        u64 acc[8];
        #pragma unroll
        for (int r = 0; r < 8; ++r) acc[r] = 0;
        #pragma unroll 4
        for (int p = 0; p < DD/4; ++p) {
            u64 w0 = wr[2*p], w1 = wr[2*p + 1];
            #pragma unroll
            for (int r = 0; r < 8; ++r) {
                double2 v = __ldg(xb + (size_t)r * (DD/4) + p);  // 16B lane-uniform broadcast
                acc[r] = ffma2((u64)__double_as_longlong(v.x), w0, acc[r]);
                acc[r] = ffma2((u64)__double_as_longlong(v.y), w1, acc[r]);
            }
        }
        if (lane < KK) {
            #pragma unroll
            for (int r = 0; r < 8; ++r) {
                float2 f = upk2(acc[r]);
                Ps[(ib + r)*KP + lane] = __expf(f.x + f.y);
            }
        }
    }
}

__device__ __forceinline__ void dp_forward(const float* Ps, float* U,
                                           const float* E, int lane)
{
    const int ll = (lane < KK) ? lane : 0;
    float Ecol[KK];
    #pragma unroll
    for (int j = 0; j < KK; ++j) Ecol[j] = E[j*KK + ll];
    float u = (lane < KK) ? 1.f : 0.f;
    if (lane < KK) U[lane] = 1.f;
    float pcur = Ps[ll];
    for (int i = 1; i < MM; ++i) {
        float tv = (lane < KK) ? u * pcur : 0.f;
        pcur = Ps[i*KP + ll];
        float a0 = 0.f, a1 = 0.f, a2 = 0.f, a3 = 0.f;
        #pragma unroll
        for (int j = 0; j < 24; j += 4) {
            a0 = fmaf(__shfl_sync(0xffffffffu, tv, j+0), Ecol[j+0], a0);
            a1 = fmaf(__shfl_sync(0xffffffffu, tv, j+1), Ecol[j+1], a1);
            a2 = fmaf(__shfl_sync(0xffffffffu, tv, j+2), Ecol[j+2], a2);
            a3 = fmaf(__shfl_sync(0xffffffffu, tv, j+3), Ecol[j+3], a3);
        }
        a0 = fmaf(__shfl_sync(0xffffffffu, tv, 24), Ecol[24], a0);
        a1 = fmaf(__shfl_sync(0xffffffffu, tv, 25), Ecol[25], a1);
        float un = (a0 + a1) + (a2 + a3);
        if ((i & 7) == 0) {
            unsigned mb = __reduce_max_sync(0xffffffffu, __float_as_uint(un));
            un *= __uint_as_float((254u - (mb >> 23)) << 23);
        }
        u = un;
        if (lane < KK) U[i*KP + lane] = u;
    }
}

__device__ __forceinline__ void dp_backward(const float* Ps, float* V, int* dexp,
                                            const float* E, int lane)
{
    const int ll = (lane < KK) ? lane : 0;
    float Erow[KK];
    #pragma unroll
    for (int j = 0; j < KK; ++j) Erow[j] = E[ll*KK + j];
    float v = (lane < KK) ? 1.f : 0.f;
    if (lane < KK) V[(MM-1)*KP + lane] = 1.f;
    float pcur = Ps[(MM-1)*KP + ll];
    for (int i = MM - 2; i >= 0; --i) {
        float rv = (lane < KK) ? v * pcur : 0.f;
        pcur = Ps[i*KP + ll];
        float a0 = 0.f, a1 = 0.f, a2 = 0.f, a3 = 0.f;
        #pragma unroll
        for (int j = 0; j < 24; j += 4) {
            a0 = fmaf(__shfl_sync(0xffffffffu, rv, j+0), Erow[j+0], a0);
            a1 = fmaf(__shfl_sync(0xffffffffu, rv, j+1), Erow[j+1], a1);
            a2 = fmaf(__shfl_sync(0xffffffffu, rv, j+2), Erow[j+2], a2);
            a3 = fmaf(__shfl_sync(0xffffffffu, rv, j+3), Erow[j+3], a3);
        }
        a0 = fmaf(__shfl_sync(0xffffffffu, rv, 24), Erow[24], a0);
        a1 = fmaf(__shfl_sync(0xffffffffu, rv, 25), Erow[25], a1);
        float vn = (a0 + a1) + (a2 + a3);
        if ((i & 7) == 0) {
            unsigned mb = __reduce_max_sync(0xffffffffu, __float_as_uint(vn));
            int fe = (int)(mb >> 23);
            vn *= __uint_as_float((unsigned)(254 - fe) << 23);
            if (lane == 0) dexp[i] = fe - 127;
        }
        v = vn;
        if (lane < KK) V[i*KP + lane] = v;
    }
}

__device__ __forceinline__ void residual_pass(float* Ps, float* U, float* V,
                                              const int* lab, const int* dexp,
                                              int u0, int nu, int lane)
{
    for (int uu = u0; uu < 128; uu += nu) {
        const int i0r = 2*uu, i1r = 2*uu + 1;
        float u0_=0.f,v0=0.f,p0=0.f,pr0=0.f, u1=0.f,v1=0.f,p1_=0.f,pr1=0.f;
        if (lane < KK) {
            u0_ = U[i0r*KP + lane]; v0 = V[i0r*KP + lane]; p0 = Ps[i0r*KP + lane];
            pr0 = u0_ * v0 * p0;
            u1 = U[i1r*KP + lane]; v1 = V[i1r*KP + lane]; p1_ = Ps[i1r*KP + lane];
            pr1 = u1 * v1 * p1_;
        }
        float z0 = pr0, z1 = pr1;
        #pragma unroll
        for (int o = 16; o; o >>= 1) {
            z0 += __shfl_xor_sync(0xffffffffu, z0, o);
            z1 += __shfl_xor_sync(0xffffffffu, z1, o);
        }
        float inv0 = 1.f / z0, inv1 = 1.f / z1;
        if (lane < KK) {
            float sc0 = __uint_as_float((unsigned)(127 - dexp[i0r]) << 23);
            float sc1 = __uint_as_float((unsigned)(127 - dexp[i1r]) << 23);
            float oh0 = (lab[i0r] == lane) ? 1.f : 0.f;
            float oh1 = (lab[i1r] == lane) ? 1.f : 0.f;
            Ps[i0r*KP + lane] = oh0 - pr0 * inv0;
            Ps[i1r*KP + lane] = oh1 - pr1 * inv1;
            U[i0r*KP + lane]  = u0_ * p0  * inv0 * sc0;
            U[i1r*KP + lane]  = u1  * p1_ * inv1 * sc1;
            V[i0r*KP + lane]  = p0  * v0;
            V[i1r*KP + lane]  = p1_ * v1;
        }
    }
}

__device__ __forceinline__ void dT_pass(const float* U, const float* V,
                                        const float* E, const int* cnt,
                                        float* outw, int tt)
{
    if (tt >= 169) return;
    const int a = tt / 13;
    const int q = tt - a * 13;
    u64 s2a = 0, s2b = 0;
    const float* Ua = U + a;
    const float* Ub = U + a + 13;
    const u64*   Vq = (const u64*)(V + 2*q);
    #pragma unroll 4
    for (int i = 0; i < MM - 1; ++i) {
        float ua = Ua[i*KP];
        float ub = Ub[i*KP];
        u64 vv = Vq[(i+1)*(KP/2)];
        s2a = ffma2(pk2(ua, ua), vv, s2a);
        s2b = ffma2(pk2(ub, ub), vv, s2b);
    }
    float2 sa = upk2(s2a), sb = upk2(s2b);
    const int b0 = 2*q;
    const int pa = a*KK + b0, pb = (a+13)*KK + b0;
    outw[KK*DD + pa]     = (float)cnt[pa]     - E[pa]     * sa.x;
    outw[KK*DD + pa + 1] = (float)cnt[pa + 1] - E[pa + 1] * sa.y;
    outw[KK*DD + pb]     = (float)cnt[pb]     - E[pb]     * sb.x;
    outw[KK*DD + pb + 1] = (float)cnt[pb + 1] - E[pb + 1] * sb.y;
}

__device__ __forceinline__ void dw_pass(const float* Ps, const float* __restrict__ x,
                                        float* outw, int tt)
{
    const int d    = tt & (DD - 1);
    const int half = tt >> 7;
    const int p0   = half * 7;
    const int np   = 7 - half;
    u64 acc[7];
    #pragma unroll
    for (int j = 0; j < 7; ++j) acc[j] = 0;
    const float* xp = x + d;
    float n0 = __ldg(xp + 0*DD), n1 = __ldg(xp + 1*DD);
    float n2 = __ldg(xp + 2*DD), n3 = __ldg(xp + 3*DD);
    for (int i = 0; i < MM; i += 4) {
        float c0 = n0, c1 = n1, c2 = n2, c3 = n3;
        if (i + 4 < MM) {
            n0 = __ldg(xp + (size_t)(i+4) * DD);
            n1 = __ldg(xp + (size_t)(i+5) * DD);
            n2 = __ldg(xp + (size_t)(i+6) * DD);
            n3 = __ldg(xp + (size_t)(i+7) * DD);
        }
        u64 xx0 = pk2(c0,c0), xx1 = pk2(c1,c1), xx2 = pk2(c2,c2), xx3 = pk2(c3,c3);
        const u64* r0 = (const u64*)(Ps + (i+0)*KP) + p0;
        const u64* r1 = (const u64*)(Ps + (i+1)*KP) + p0;
        const u64* r2 = (const u64*)(Ps + (i+2)*KP) + p0;
        const u64* r3 = (const u64*)(Ps + (i+3)*KP) + p0;
        #pragma unroll
        for (int j = 0; j < 7; ++j) {
            if (j < np) {
                acc[j] = ffma2(r0[j], xx0, acc[j]);
                acc[j] = ffma2(r1[j], xx1, acc[j]);
                acc[j] = ffma2(r2[j], xx2, acc[j]);
                acc[j] = ffma2(r3[j], xx3, acc[j]);
            }
        }
    }
    #pragma unroll
    for (int j = 0; j < 7; ++j) {
        if (j < np) {
            float2 f = upk2(acc[j]);
            const int k = 2 * (p0 + j);
            outw[(k)     * DD + d] = f.x;
            outw[(k + 1) * DD + d] = f.y;
        }
    }
}

// ================= kernel =================

__global__ void __launch_bounds__(NT, 1)
crf_fused_kernel(const float* __restrict__ data,
                 const int* __restrict__ labI,
                 const float* __restrict__ Wg,
                 const float* __restrict__ Tg,
                 float* __restrict__ out)
{
    extern __shared__ float sm[];
    const int t    = threadIdx.x;
    const int lane = t & 31;
    const int wid  = t >> 5;

    // ================= REDUCER BLOCKS =================
    if (blockIdx.x >= WB) {
        if (t == 0) {
            while (ld_vol(&g_ctr) < BB) __nanosleep(200);
        }
        __syncthreads();
        __threadfence();   // acquire

        float* red = sm;   // [8][33]
        const int ws = wid;
        const int og = (blockIdx.x - WB) * 32 + lane;
        if (ws < 8) {
            float s0 = 0.f, s1 = 0.f, s2 = 0.f, s3 = 0.f;
            if (og < OUTSZ) {
                const float* p = g_scratch + (size_t)ws * 64 * OUTSZ + og;
                #pragma unroll 4
                for (int v = 0; v < 64; v += 4) {
                    s0 += p[(size_t)(v + 0) * OUTSZ];
                    s1 += p[(size_t)(v + 1) * OUTSZ];
                    s2 += p[(size_t)(v + 2) * OUTSZ];
                    s3 += p[(size_t)(v + 3) * OUTSZ];
                }
            }
            red[ws * 33 + lane] = (s0 + s1) + (s2 + s3);
        }
        __syncthreads();
        if (ws == 0 && og < OUTSZ) {
            float tot = 0.f;
            #pragma unroll
            for (int j = 0; j < 8; ++j) tot += red[j * 33 + lane];
            out[og] = tot * (1.0f / BB);
        }
        __threadfence();
        __syncthreads();
        if (t == 0) {
            if (atomicAdd(&g_done, 1) == NRED - 1) {   // last reducer resets for replay
                g_ctr  = 0;
                g_done = 0;
            }
        }
        return;
    }

    // ================= WORD-PAIR BLOCKS =================
    float* PsA = sm + SM_PSA; float* UA = sm + SM_UA; float* VA = sm + SM_VA;
    float* PsB = sm + SM_PSB; float* UB = sm + SM_UB; float* VB = sm + SM_VB;
    float* Wsh = sm + SM_VB;           // alias: dead before DP_B writes V_B
    float* E   = sm + SM_E;
    int* labA  = (int*)(sm + SM_LABA);
    int* labB  = (int*)(sm + SM_LABB);
    int* dexpA = (int*)(sm + SM_DEA);
    int* dexpB = (int*)(sm + SM_DEB);
    int* cntA  = (int*)(sm + SM_CNTA);
    int* cntB  = (int*)(sm + SM_CNTB);
    __shared__ int s_is64;

    const int wA = 2 * blockIdx.x;
    const int wBw = wA + 1;
    const float* xA = data + (size_t)wA  * MM * DD;
    const float* xB = data + (size_t)wBw * MM * DD;

    // ---- detect labels dtype ----
    if (t == 0) s_is64 = 1;
    __syncthreads();
    if (labI[2*t + 1] != 0) atomicAnd(&s_is64, 0);

    // ---- init ----
    for (int p = t; p < KK*KK; p += NT) { E[p] = __expf(Tg[p]); cntA[p] = 0; cntB[p] = 0; }
    for (int p = t; p < KK*DD; p += NT) Wsh[(p / DD) * WPAD + (p % DD)] = Wg[p];
    for (int p = t; p < MM;    p += NT) { dexpA[p] = 0; dexpB[p] = 0; }
    __syncthreads();
    const int is64 = s_is64;
    for (int p = t; p < MM; p += NT) {
        labA[p] = is64 ? labI[((size_t)wA *MM + p) * 2] : labI[(size_t)wA *MM + p];
        labB[p] = is64 ? labI[((size_t)wBw*MM + p) * 2] : labI[(size_t)wBw*MM + p];
    }
    __syncthreads();
    if (t < MM - 1) {
        atomicAdd(&cntA[labA[t]*KK + labA[t+1]], 1);
        atomicAdd(&cntB[labB[t]*KK + labB[t+1]], 1);
    }

    // ---- phase 2: S_A on all 16 warps ----
    phase_S(xA, PsA, Wsh, wid, 16, lane);
    __syncthreads();

    // ---- phase 3: DP_A (w0,w1) || S_B (w2..w15) ----
    if (wid == 0)      dp_forward (PsA, UA, E, lane);
    else if (wid == 1) dp_backward(PsA, VA, dexpA, E, lane);
    else               phase_S(xB, PsB, Wsh, wid - 2, 14, lane);
    __syncthreads();

    float* outwA = g_scratch + (size_t)wA  * OUTSZ;
    float* outwB = g_scratch + (size_t)wBw * OUTSZ;

    // ---- phase 4: DP_B (w0,w1) || [residual_A; bar1; dw_A (w2-9) || dT_A (w10-15)] ----
    if (wid == 0)      dp_forward (PsB, UB, E, lane);
    else if (wid == 1) dp_backward(PsB, VB, dexpB, E, lane);
    else {
        residual_pass(PsA, UA, VA, labA, dexpA, wid - 2, 14, lane);
        asm volatile("bar.sync 1, 448;" ::: "memory");   // warps 2..15 only (448 arrivals)
        if (wid < 10) dw_pass(PsA, xA, outwA, t - 64);
        else          dT_pass(UA, VA, E, cntA, outwA, t - 320);
    }
    __syncthreads();

    // ---- phase 5: residual_B on all 16 warps ----
    residual_pass(PsB, UB, VB, labB, dexpB, wid, 16, lane);
    __syncthreads();

    // ---- phase 6: dw_B (t<256) || dT_B (t in [256,448)) ----
    if (t < 256)      dw_pass(PsB, xB, outwB, t);
    else if (t < 448) dT_pass(UB, VB, E, cntB, outwB, t - 256);

    // ---- doorbell: both words done ----
    __syncthreads();
    if (t == 0) {
        __threadfence();              // release scratch writes
        atomicAdd(&g_ctr, 2);
    }
}

extern "C" void kernel_launch(void* const* d_in, const int* in_sizes, int n_in,
                              void* d_out, int out_size)
{
    const float* data   = (const float*)d_in[0];
    const int*   labels = (const int*)d_in[1];
    const float* W      = (const float*)d_in[2];
    const float* T      = (const float*)d_in[3];
    float* out = (float*)d_out;

    const size_t smem = SM_TOT * sizeof(float);
    cudaFuncSetAttribute(crf_fused_kernel,
                         cudaFuncAttributeMaxDynamicSharedMemorySize, (int)smem);
    crf_fused_kernel<<<WB + NRED, NT, smem>>>(data, labels, W, T, out);
}